// round 6
// baseline (speedup 1.0000x reference)
#include <cuda_runtime.h>
#include <cuda_bf16.h>

// Problem shapes (fixed by reference setup_inputs)
#define B    4
#define CIN  512
#define OUT  256
#define NN   4096

#define CLUSTER 16              // nonportable cluster size (opt-in attribute set at launch)
#define TPB     512             // 16 warps
#define GRID    (B * CLUSTER)   // 64 CTAs = 4 clusters, one cluster per batch

// Scratch (no cudaMalloc allowed); fully overwritten every run
__device__ float g_X[B * CIN];

// One kernel, one launch:
//  phase 1: cluster (= batch b) reduces its 512 channel rows -> g_X[b,:]
//  barrier.cluster (release/acquire), phase-2 reads via __ldcg (L1-safe)
//  phase 2: warp (rank,w) owns output row o = rank*16+w: dot + elu + stream
__global__ void __cluster_dims__(CLUSTER, 1, 1) __launch_bounds__(TPB, 1)
k_all(const float* __restrict__ x, const float* __restrict__ W1,
      float* __restrict__ out) {
    const int t    = threadIdx.x;
    const int warp = t >> 5;            // 0..15
    const int lane = t & 31;
    const int blk  = blockIdx.x;
    const int b    = blk >> 4;          // batch     (cluster id)
    const int rank = blk & 15;          // cluster rank

    // ---------------- phase 1: 32 rows per CTA, 2 rows per warp ----------------
    const int c0 = rank * 32 + warp * 2;
    #pragma unroll
    for (int r = 0; r < 2; r++) {
        const int row = b * CIN + c0 + r;
        const float4* __restrict__ p =
            reinterpret_cast<const float4*>(x) + (size_t)row * (NN / 4);
        float s = 0.f;
        #pragma unroll
        for (int g = 0; g < 4; g++) {           // 4 groups of 8 in-flight loads
            float4 v[8];
            #pragma unroll
            for (int i = 0; i < 8; i++) v[i] = p[lane + (g * 8 + i) * 32];
            #pragma unroll
            for (int i = 0; i < 8; i++) s += (v[i].x + v[i].y) + (v[i].z + v[i].w);
        }
        #pragma unroll
        for (int off = 16; off > 0; off >>= 1)
            s += __shfl_down_sync(0xffffffffu, s, off);
        if (lane == 0) g_X[row] = s;
    }

    // ---------------- cluster barrier (covers all writers of X[b,:]) ----------
    __threadfence();   // publish g_X stores (gpu scope; belt + suspenders)
    asm volatile("barrier.cluster.arrive.aligned;" ::: "memory");
    asm volatile("barrier.cluster.wait.aligned;" ::: "memory");

    // ---------------- phase 2: one output row per warp ------------------------
    const int o = rank * 16 + warp;             // 0..255
    const float4* __restrict__ wr =
        reinterpret_cast<const float4*>(W1) + (size_t)o * (CIN / 4);
    const float4* __restrict__ xr =
        reinterpret_cast<const float4*>(g_X) + (size_t)b * (CIN / 4);

    float4 a0 = wr[lane];       float4 a1 = wr[lane + 32];
    float4 a2 = wr[lane + 64];  float4 a3 = wr[lane + 96];
    float4 b0 = __ldcg(xr + lane);       float4 b1 = __ldcg(xr + lane + 32);
    float4 b2 = __ldcg(xr + lane + 64);  float4 b3 = __ldcg(xr + lane + 96);

    float s0 = fmaf(a0.x, b0.x, fmaf(a0.y, b0.y, fmaf(a0.z, b0.z, a0.w * b0.w)));
    float s1 = fmaf(a1.x, b1.x, fmaf(a1.y, b1.y, fmaf(a1.z, b1.z, a1.w * b1.w)));
    float s2 = fmaf(a2.x, b2.x, fmaf(a2.y, b2.y, fmaf(a2.z, b2.z, a2.w * b2.w)));
    float s3 = fmaf(a3.x, b3.x, fmaf(a3.y, b3.y, fmaf(a3.z, b3.z, a3.w * b3.w)));
    float s  = (s0 + s1) + (s2 + s3);

    #pragma unroll
    for (int off = 16; off > 0; off >>= 1)      // butterfly: all lanes get sum
        s += __shfl_xor_sync(0xffffffffu, s, off);

    const float  e  = (s > 0.f) ? s : expm1f(s);   // elu, alpha=1
    const float4 v4 = make_float4(e, e, e, e);

    float4* __restrict__ q =
        reinterpret_cast<float4*>(out) + (size_t)(b * OUT + o) * (NN / 4);
    #pragma unroll
    for (int i = 0; i < 32; i++)                 // 1024 float4 / 32 lanes
        q[lane + i * 32] = v4;
}

extern "C" void kernel_launch(void* const* d_in, const int* in_sizes, int n_in,
                              void* d_out, int out_size) {
    const float* x  = (const float*)d_in[0];   // [B, CIN, 1, NN]
    const float* W1 = (const float*)d_in[1];   // [OUT, CIN]
    // d_in[2] = w2, d_in[3] = bias_mat: unused (softmax over size-1 axis == 1)
    float* out = (float*)d_out;                // [B, OUT, 1, NN]

    // Opt in to cluster size 16 (idempotent; not a stream op, capture-safe)
    cudaFuncSetAttribute(k_all, cudaFuncAttributeNonPortableClusterSizeAllowed, 1);

    k_all<<<GRID, TPB>>>(x, W1, out);
}

// round 7
// speedup vs baseline: 1.3862x; 1.3862x over previous
#include <cuda_runtime.h>
#include <cuda_bf16.h>

// Problem shapes (fixed by reference setup_inputs)
#define B    4
#define CIN  512
#define OUT  256
#define NN   4096

// Scratch (no cudaMalloc allowed); fully overwritten every run
__device__ float g_X[B * CIN];   // X[b,c] = sum_n x[b,c,n]

// ---------------------------------------------------------------------------
// Kernel 1: reduce x over N. One block per (b,c) row (16 KB each).
// 256 threads x 4 front-batched float4. Triggers PDL completion at the end.
// ---------------------------------------------------------------------------
__global__ __launch_bounds__(256) void k_rowsum(const float* __restrict__ x) {
    const int row = blockIdx.x;                 // 0 .. B*CIN-1
    const float4* __restrict__ p =
        reinterpret_cast<const float4*>(x + (size_t)row * NN);
    const int t = threadIdx.x;

    float4 v0 = p[t];
    float4 v1 = p[t + 256];
    float4 v2 = p[t + 512];
    float4 v3 = p[t + 768];

    float s0 = (v0.x + v0.y) + (v0.z + v0.w);
    float s1 = (v1.x + v1.y) + (v1.z + v1.w);
    float s2 = (v2.x + v2.y) + (v2.z + v2.w);
    float s3 = (v3.x + v3.y) + (v3.z + v3.w);
    float s  = (s0 + s1) + (s2 + s3);

    #pragma unroll
    for (int off = 16; off > 0; off >>= 1)
        s += __shfl_down_sync(0xffffffffu, s, off);

    __shared__ float sm[8];
    if ((t & 31) == 0) sm[t >> 5] = s;
    __syncthreads();
    if (t < 8) {
        float u = sm[t];
        #pragma unroll
        for (int off = 4; off > 0; off >>= 1)
            u += __shfl_down_sync(0xffu, u, off);
        if (t == 0) g_X[row] = u;
    }

    // Allow the dependent kernel to start mounting / running its prologue.
    cudaTriggerProgrammaticLaunchCompletion();
}

// ---------------------------------------------------------------------------
// Kernel 2: 1024 blocks x 256 threads, one output row per block.
// Every warp REDUNDANTLY computes the row's 512-dot (L1/L2-hot, trivial cost)
// -> no __syncthreads, no shared memory, 8 fully independent store streams.
// PDL: W1 prologue runs before cudaGridDependencySynchronize().
// ---------------------------------------------------------------------------
__global__ __launch_bounds__(256) void k_out(const float* __restrict__ W1,
                                             float* __restrict__ out) {
    const int bo   = blockIdx.x;       // 0 .. 1023
    const int b    = bo >> 8;          // OUT = 256
    const int o    = bo & 255;
    const int warp = threadIdx.x >> 5; // 0..7
    const int lane = threadIdx.x & 31;

    // ---- prologue (independent of k_rowsum): load W1 row ----
    const float4* __restrict__ wr =
        reinterpret_cast<const float4*>(W1) + (size_t)o * (CIN / 4);
    float4 a0 = wr[lane];       float4 a1 = wr[lane + 32];
    float4 a2 = wr[lane + 64];  float4 a3 = wr[lane + 96];

    // ---- wait for k_rowsum's memory to be visible ----
    cudaGridDependencySynchronize();

    const float4* __restrict__ xr =
        reinterpret_cast<const float4*>(g_X) + (size_t)b * (CIN / 4);
    float4 b0 = xr[lane];       float4 b1 = xr[lane + 32];
    float4 b2 = xr[lane + 64];  float4 b3 = xr[lane + 96];

    float s0 = fmaf(a0.x, b0.x, fmaf(a0.y, b0.y, fmaf(a0.z, b0.z, a0.w * b0.w)));
    float s1 = fmaf(a1.x, b1.x, fmaf(a1.y, b1.y, fmaf(a1.z, b1.z, a1.w * b1.w)));
    float s2 = fmaf(a2.x, b2.x, fmaf(a2.y, b2.y, fmaf(a2.z, b2.z, a2.w * b2.w)));
    float s3 = fmaf(a3.x, b3.x, fmaf(a3.y, b3.y, fmaf(a3.z, b3.z, a3.w * b3.w)));
    float s  = (s0 + s1) + (s2 + s3);

    #pragma unroll
    for (int off = 16; off > 0; off >>= 1)     // butterfly: all lanes get sum
        s += __shfl_xor_sync(0xffffffffu, s, off);

    const float  e  = (s > 0.f) ? s : expm1f(s);   // elu, alpha=1
    const float4 v4 = make_float4(e, e, e, e);

    // warp owns float4 indices [warp*128, warp*128+128) of this 1024-f4 row
    float4* __restrict__ q =
        reinterpret_cast<float4*>(out) + (size_t)bo * (NN / 4) + warp * 128;
    q[lane]      = v4;
    q[lane + 32] = v4;
    q[lane + 64] = v4;
    q[lane + 96] = v4;
}

extern "C" void kernel_launch(void* const* d_in, const int* in_sizes, int n_in,
                              void* d_out, int out_size) {
    const float* x  = (const float*)d_in[0];   // [B, CIN, 1, NN]
    const float* W1 = (const float*)d_in[1];   // [OUT, CIN]
    // d_in[2] = w2, d_in[3] = bias_mat: unused (softmax over size-1 axis == 1)
    float* out = (float*)d_out;                // [B, OUT, 1, NN]

    k_rowsum<<<B * CIN, 256>>>(x);

    // Secondary launch with Programmatic Stream Serialization (PDL overlap).
    cudaLaunchConfig_t cfg = {};
    cfg.gridDim  = dim3(B * OUT, 1, 1);
    cfg.blockDim = dim3(256, 1, 1);
    cfg.dynamicSmemBytes = 0;
    cfg.stream = 0;
    cudaLaunchAttribute attr[1];
    attr[0].id = cudaLaunchAttributeProgrammaticStreamSerialization;
    attr[0].val.programmaticStreamSerializationAllowed = 1;
    cfg.attrs = attr;
    cfg.numAttrs = 1;
    cudaLaunchKernelEx(&cfg, k_out, W1, out);
}